// round 5
// baseline (speedup 1.0000x reference)
#include <cuda_runtime.h>
#include <math.h>

// ---------------------------------------------------------------------------
// PGA(3,0,1) blade algebra, computed at compile time.
// Blade index order (matches reference BLADES):
//  0:()  1:e0  2:e1  3:e2  4:e3  5:e01 6:e02 7:e03 8:e12 9:e13 10:e23
//  11:e012 12:e013 13:e023 14:e123 15:e0123
// ---------------------------------------------------------------------------

__host__ __device__ constexpr int pc4(int x) {
    return ((x >> 0) & 1) + ((x >> 1) & 1) + ((x >> 2) & 1) + ((x >> 3) & 1);
}

__host__ __device__ constexpr int I2M(int i) {
    return (i == 0) ? 0  : (i == 1) ? 1  : (i == 2) ? 2  : (i == 3) ? 4  :
           (i == 4) ? 8  : (i == 5) ? 3  : (i == 6) ? 5  : (i == 7) ? 9  :
           (i == 8) ? 6  : (i == 9) ? 10 : (i == 10) ? 12 : (i == 11) ? 7 :
           (i == 12) ? 11 : (i == 13) ? 13 : (i == 14) ? 14 : 15;
}

__host__ __device__ constexpr int M2I(int m) {
    return (m == 0) ? 0  : (m == 1) ? 1  : (m == 2) ? 2  : (m == 3) ? 5  :
           (m == 4) ? 3  : (m == 5) ? 6  : (m == 6) ? 8  : (m == 7) ? 11 :
           (m == 8) ? 4  : (m == 9) ? 7  : (m == 10) ? 9 : (m == 11) ? 12 :
           (m == 12) ? 10 : (m == 13) ? 13 : (m == 14) ? 14 : 15;
}

__host__ __device__ constexpr int msign(int a, int b) {
    int s = 0;
    if ((b >> 0) & 1) s += pc4(a >> 1);
    if ((b >> 1) & 1) s += pc4(a >> 2);
    if ((b >> 2) & 1) s += pc4(a >> 3);
    return (s & 1) ? -1 : 1;
}

__host__ __device__ constexpr int dsign(int m) { return msign(m, 15 ^ m); }

__host__ __device__ constexpr int jsign(int ma, int mb) {
    return dsign(ma) * dsign(mb) * msign(15 ^ ma, 15 ^ mb) * dsign(ma & mb);
}

// ---------------------------------------------------------------------------
// Packed 2xfp32 helpers (Blackwell FFMA2 path — PTX-only, ptxas won't fuse).
// ---------------------------------------------------------------------------
typedef unsigned long long u64;

#define FMA2(d, a, b, c) asm("fma.rn.f32x2 %0, %1, %2, %3;" : "=l"(d) : "l"(a), "l"(b), "l"(c))
#define MUL2(d, a, b)    asm("mul.rn.f32x2 %0, %1, %2;"     : "=l"(d) : "l"(a), "l"(b))

__device__ __forceinline__ u64 pk(float l_, float h_) {
    u64 r; asm("mov.b64 %0, {%1, %2};" : "=l"(r) : "f"(l_), "f"(h_)); return r;
}
__device__ __forceinline__ void upk(float& l_, float& h_, u64 v) {
    asm("mov.b64 {%0, %1}, %2;" : "=f"(l_), "=f"(h_) : "l"(v));
}
__device__ __forceinline__ u64 bcast(float s) { return pk(s, s); }

// ---------------------------------------------------------------------------
// 128 threads per block, 2 tokens per thread (block covers 256 tokens).
// Token A = base + tid, token B = base + tid + 128. All multivector state is
// packed f32x2 (lo = A, hi = B): halves the math-instruction count per token.
// ---------------------------------------------------------------------------
__global__ void __launch_bounds__(128)
mvffn_kernel(const float* __restrict__ x,
             const float* __restrict__ w1, const float* __restrict__ v1, const float* __restrict__ b1,
             const float* __restrict__ wg, const float* __restrict__ vg, const float* __restrict__ bg,
             const float* __restrict__ wj, const float* __restrict__ vj, const float* __restrict__ bj,
             float* __restrict__ out, int ntok)
{
    const int tid = threadIdx.x;
    int tA = blockIdx.x * 256 + tid;
    if (tA >= ntok) return;
    int tB = tA + 128;
    const bool hasB = (tB < ntok);
    if (!hasB) tB = tA;                      // duplicate lane; B store skipped

    const float4* A4 = reinterpret_cast<const float4*>(x) + (size_t)tA * 4;
    const float4* B4 = reinterpret_cast<const float4*>(x) + (size_t)tB * 4;
    float4 a0 = A4[0], a1 = A4[1], a2 = A4[2], a3 = A4[3];
    float4 b0 = B4[0], b1q = B4[1], b2 = B4[2], b3 = B4[3];

    u64 xn[16];
    xn[0]  = pk(a0.x, b0.x);  xn[1]  = pk(a0.y, b0.y);
    xn[2]  = pk(a0.z, b0.z);  xn[3]  = pk(a0.w, b0.w);
    xn[4]  = pk(a1.x, b1q.x); xn[5]  = pk(a1.y, b1q.y);
    xn[6]  = pk(a1.z, b1q.z); xn[7]  = pk(a1.w, b1q.w);
    xn[8]  = pk(a2.x, b2.x);  xn[9]  = pk(a2.y, b2.y);
    xn[10] = pk(a2.z, b2.z);  xn[11] = pk(a2.w, b2.w);
    xn[12] = pk(a3.x, b3.x);  xn[13] = pk(a3.y, b3.y);
    xn[14] = pk(a3.z, b3.z);  xn[15] = pk(a3.w, b3.w);

    // ---- normalize over non-e0 blades: idx 0,2,3,4,8,9,10,14 ----
    u64 s2 = pk(1e-5f, 1e-5f);
    FMA2(s2, xn[0],  xn[0],  s2);
    FMA2(s2, xn[2],  xn[2],  s2);
    FMA2(s2, xn[3],  xn[3],  s2);
    FMA2(s2, xn[4],  xn[4],  s2);
    FMA2(s2, xn[8],  xn[8],  s2);
    FMA2(s2, xn[9],  xn[9],  s2);
    FMA2(s2, xn[10], xn[10], s2);
    FMA2(s2, xn[14], xn[14], s2);
    float sA, sB;  upk(sA, sB, s2);
    float rA = rsqrtf(sA), rB = rsqrtf(sB);
    u64 rinv2 = pk(rA, rB);
    u64 nrm2  = pk(sA * rA, sB * rB);        // sqrt(s): residual x = xn*nrm
    #pragma unroll
    for (int d = 0; d < 16; d++) MUL2(xn[d], xn[d], rinv2);

    // ---- first linear weights + exact GELU gate, gate folded into weights ----
    const float4 w1a = *reinterpret_cast<const float4*>(w1);
    const float  w1e = w1[4];
    const float4 v1a = *reinterpret_cast<const float4*>(v1);

    u64 xp0_2;
    FMA2(xp0_2, bcast(w1a.x), xn[0], bcast(b1[0]));
    float xpA, xpB;  upk(xpA, xpB, xp0_2);
    u64 gate2 = pk(xpA * normcdff(xpA), xpB * normcdff(xpB));

    u64 W1[5], V1[4], xg0_2;
    MUL2(W1[0], gate2, bcast(w1a.x));
    MUL2(W1[1], gate2, bcast(w1a.y));
    MUL2(W1[2], gate2, bcast(w1a.z));
    MUL2(W1[3], gate2, bcast(w1a.w));
    MUL2(W1[4], gate2, bcast(w1e));
    MUL2(V1[0], gate2, bcast(v1a.x));
    MUL2(V1[1], gate2, bcast(v1a.y));
    MUL2(V1[2], gate2, bcast(v1a.z));
    MUL2(V1[3], gate2, bcast(v1a.w));
    MUL2(xg0_2, gate2, xp0_2);               // xg[0] (bias included)

    const u64 NEG1 = pk(-1.f, -1.f);

    // ---- geometric product + join, j-outer / i-inner, xg[j] on the fly ----
    u64 gp[16], jn[16];
    #pragma unroll
    for (int k = 0; k < 16; k++) { gp[k] = 0ull; jn[k] = 0ull; }  // 0 bits == (0.f,0.f)

    #pragma unroll
    for (int j = 0; j < 16; j++) {
        const int mb = I2M(j);
        const int gB = pc4(mb);

        u64 xgj;
        if (j == 0) {
            xgj = xg0_2;
        } else {
            MUL2(xgj, W1[gB], xn[j]);
            if ((mb & 1) && gB < 4) FMA2(xgj, V1[gB], xn[M2I(mb ^ 1)], xgj);
        }
        u64 nxgj;
        MUL2(nxgj, xgj, NEG1);

        #pragma unroll
        for (int i = 0; i < 16; i++) {
            const int ma = I2M(i);
            if (!(ma & mb & 1)) {                          // e0^2 = 0
                const int k = M2I(ma ^ mb);
                const u64 op = (msign(ma, mb) > 0) ? xgj : nxgj;
                FMA2(gp[k], xn[i], op, gp[k]);
            }
            if ((ma | mb) == 15) {                         // join support
                const int k = M2I(ma & mb);
                const u64 op = (jsign(ma, mb) > 0) ? xgj : nxgj;
                FMA2(jn[k], xn[i], op, jn[k]);
            }
        }
    }

    // ---- output linears (x15 folded into join weights) + residual ----
    const float4 wga = *reinterpret_cast<const float4*>(wg);
    const float  wge = wg[4];
    const float4 vga = *reinterpret_cast<const float4*>(vg);
    const float4 wja = *reinterpret_cast<const float4*>(wj);
    const float  wje = wj[4];
    const float4 vja = *reinterpret_cast<const float4*>(vj);

    const u64 x15_2 = xn[15];
    u64 WG[5], VG[4], WJ[5], VJ[4];
    WG[0] = bcast(wga.x); WG[1] = bcast(wga.y); WG[2] = bcast(wga.z);
    WG[3] = bcast(wga.w); WG[4] = bcast(wge);
    VG[0] = bcast(vga.x); VG[1] = bcast(vga.y); VG[2] = bcast(vga.z);
    VG[3] = bcast(vga.w);
    MUL2(WJ[0], bcast(wja.x), x15_2);
    MUL2(WJ[1], bcast(wja.y), x15_2);
    MUL2(WJ[2], bcast(wja.z), x15_2);
    MUL2(WJ[3], bcast(wja.w), x15_2);
    MUL2(WJ[4], bcast(wje),   x15_2);
    MUL2(VJ[0], bcast(vja.x), x15_2);
    MUL2(VJ[1], bcast(vja.y), x15_2);
    MUL2(VJ[2], bcast(vja.z), x15_2);
    MUL2(VJ[3], bcast(vja.w), x15_2);

    u64 o[16];
    #pragma unroll
    for (int d = 0; d < 16; d++) {
        const int m = I2M(d);
        const int g = pc4(m);
        u64 v;
        MUL2(v, xn[d], nrm2);                // residual: original x[d]
        FMA2(v, WG[g], gp[d], v);
        FMA2(v, WJ[g], jn[d], v);
        if ((m & 1) && g < 4) {
            const int sidx = M2I(m ^ 1);
            FMA2(v, VG[g], gp[sidx], v);
            FMA2(v, VJ[g], jn[sidx], v);
        }
        o[d] = v;
    }
    {
        u64 bias2 = bcast(bg[0] + bj[0]);
        u64 one2  = pk(1.f, 1.f);
        FMA2(o[0], bias2, one2, o[0]);
    }

    // ---- unpack + store both tokens ----
    float oA[16], oB[16];
    #pragma unroll
    for (int d = 0; d < 16; d++) upk(oA[d], oB[d], o[d]);

    float4* Ao = reinterpret_cast<float4*>(out) + (size_t)tA * 4;
    Ao[0] = make_float4(oA[0],  oA[1],  oA[2],  oA[3]);
    Ao[1] = make_float4(oA[4],  oA[5],  oA[6],  oA[7]);
    Ao[2] = make_float4(oA[8],  oA[9],  oA[10], oA[11]);
    Ao[3] = make_float4(oA[12], oA[13], oA[14], oA[15]);

    if (hasB) {
        float4* Bo = reinterpret_cast<float4*>(out) + (size_t)tB * 4;
        Bo[0] = make_float4(oB[0],  oB[1],  oB[2],  oB[3]);
        Bo[1] = make_float4(oB[4],  oB[5],  oB[6],  oB[7]);
        Bo[2] = make_float4(oB[8],  oB[9],  oB[10], oB[11]);
        Bo[3] = make_float4(oB[12], oB[13], oB[14], oB[15]);
    }
}

extern "C" void kernel_launch(void* const* d_in, const int* in_sizes, int n_in,
                              void* d_out, int out_size)
{
    const float* x  = (const float*)d_in[0];
    const float* w1 = (const float*)d_in[1];
    const float* v1 = (const float*)d_in[2];
    const float* b1 = (const float*)d_in[3];
    const float* wg = (const float*)d_in[4];
    const float* vg = (const float*)d_in[5];
    const float* bg = (const float*)d_in[6];
    const float* wj = (const float*)d_in[7];
    const float* vj = (const float*)d_in[8];
    const float* bj = (const float*)d_in[9];

    const int ntok   = in_sizes[0] / 16;
    const int blocks = (ntok + 255) / 256;   // 128 threads, 2 tokens/thread

    mvffn_kernel<<<blocks, 128>>>(x, w1, v1, b1, wg, vg, bg, wj, vj, bj,
                                  (float*)d_out, ntok);
}

// round 6
// speedup vs baseline: 1.0197x; 1.0197x over previous
#include <cuda_runtime.h>
#include <math.h>

// ---------------------------------------------------------------------------
// PGA(3,0,1) blade algebra, computed at compile time.
// Blade order: 0:() 1:e0 2:e1 3:e2 4:e3 5:e01 6:e02 7:e03 8:e12 9:e13 10:e23
//              11:e012 12:e013 13:e023 14:e123 15:e0123
// ---------------------------------------------------------------------------

__host__ __device__ constexpr int pc4(int x) {
    return ((x >> 0) & 1) + ((x >> 1) & 1) + ((x >> 2) & 1) + ((x >> 3) & 1);
}

__host__ __device__ constexpr int I2M(int i) {
    return (i == 0) ? 0  : (i == 1) ? 1  : (i == 2) ? 2  : (i == 3) ? 4  :
           (i == 4) ? 8  : (i == 5) ? 3  : (i == 6) ? 5  : (i == 7) ? 9  :
           (i == 8) ? 6  : (i == 9) ? 10 : (i == 10) ? 12 : (i == 11) ? 7 :
           (i == 12) ? 11 : (i == 13) ? 13 : (i == 14) ? 14 : 15;
}

__host__ __device__ constexpr int M2I(int m) {
    return (m == 0) ? 0  : (m == 1) ? 1  : (m == 2) ? 2  : (m == 3) ? 5  :
           (m == 4) ? 3  : (m == 5) ? 6  : (m == 6) ? 8  : (m == 7) ? 11 :
           (m == 8) ? 4  : (m == 9) ? 7  : (m == 10) ? 9 : (m == 11) ? 12 :
           (m == 12) ? 10 : (m == 13) ? 13 : (m == 14) ? 14 : 15;
}

__host__ __device__ constexpr int msign(int a, int b) {
    int s = 0;
    if ((b >> 0) & 1) s += pc4(a >> 1);
    if ((b >> 1) & 1) s += pc4(a >> 2);
    if ((b >> 2) & 1) s += pc4(a >> 3);
    return (s & 1) ? -1 : 1;
}

__host__ __device__ constexpr int dsign(int m) { return msign(m, 15 ^ m); }

__host__ __device__ constexpr int jsign(int ma, int mb) {
    return dsign(ma) * dsign(mb) * msign(15 ^ ma, 15 ^ mb) * dsign(ma & mb);
}

// ---------------------------------------------------------------------------
// Packed 2xfp32 helpers (Blackwell FFMA2 path — PTX-only).
// ---------------------------------------------------------------------------
typedef unsigned long long u64;

#define FMA2(d, a, b, c) asm("fma.rn.f32x2 %0, %1, %2, %3;" : "=l"(d) : "l"(a), "l"(b), "l"(c))
#define MUL2(d, a, b)    asm("mul.rn.f32x2 %0, %1, %2;"     : "=l"(d) : "l"(a), "l"(b))

__device__ __forceinline__ u64 pk(float l_, float h_) {
    u64 r; asm("mov.b64 %0, {%1, %2};" : "=l"(r) : "f"(l_), "f"(h_)); return r;
}
__device__ __forceinline__ void upk(float& l_, float& h_, u64 v) {
    asm("mov.b64 {%0, %1}, %2;" : "=f"(l_), "=f"(h_) : "l"(v));
}
__device__ __forceinline__ u64 bcast(float s) { return pk(s, s); }

// ---------------------------------------------------------------------------
// 128 threads / block, 256 tokens / block (2 tokens per thread, packed f32x2:
// lo = token tid, hi = token tid+128). Global I/O is staged through a
// swizzled smem buffer so every LDG/STG is fully coalesced (4 L1 wavefronts
// per request instead of 16).
//
// Swizzle: token t chunk c -> smem4[4t + (c ^ ((t>>1)&3))]. Conflict-free for
// both the coalesced phase (consecutive f stay in distinct 16B groups) and
// the per-token phase (verified: groups {0,4,1,5,2,6,3,7} per 8-thread phase).
// ---------------------------------------------------------------------------
#define THREADS 128
#define TOKS    256

__device__ __forceinline__ int swz(int t, int c) {
    return 4 * t + (c ^ ((t >> 1) & 3));
}

__global__ void __launch_bounds__(THREADS)
mvffn_kernel(const float* __restrict__ x,
             const float* __restrict__ w1, const float* __restrict__ v1, const float* __restrict__ b1,
             const float* __restrict__ wg, const float* __restrict__ vg, const float* __restrict__ bg,
             const float* __restrict__ wj, const float* __restrict__ vj, const float* __restrict__ bj,
             float* __restrict__ out, int ntok)
{
    __shared__ float4 stage[TOKS * 4];

    const int tid  = threadIdx.x;
    const int base = blockIdx.x * TOKS;
    const float4* xin4 = reinterpret_cast<const float4*>(x)  + (size_t)base * 4;
    float4*       out4 = reinterpret_cast<float4*>(out)      + (size_t)base * 4;
    const int     nf4  = min(TOKS, ntok - base) * 4;

    // ---- coalesced load -> swizzled smem ----
    #pragma unroll
    for (int k = 0; k < 8; k++) {
        int f = tid + k * THREADS;
        if (f < nf4) stage[swz(f >> 2, f & 3)] = xin4[f];
    }
    __syncthreads();

    const int tA = base + tid;            // lo lane
    const int tB = tA + THREADS;          // hi lane
    const bool active = (tA < ntok);
    const bool hasB   = (tB < ntok);

    if (active) {
        const int lB = hasB ? tid + THREADS : tid;   // duplicate A if no B
        float4 a0 = stage[swz(tid, 0)], a1 = stage[swz(tid, 1)];
        float4 a2 = stage[swz(tid, 2)], a3 = stage[swz(tid, 3)];
        float4 c0 = stage[swz(lB, 0)],  c1 = stage[swz(lB, 1)];
        float4 c2 = stage[swz(lB, 2)],  c3 = stage[swz(lB, 3)];

        u64 xn[16];
        xn[0]  = pk(a0.x, c0.x);  xn[1]  = pk(a0.y, c0.y);
        xn[2]  = pk(a0.z, c0.z);  xn[3]  = pk(a0.w, c0.w);
        xn[4]  = pk(a1.x, c1.x);  xn[5]  = pk(a1.y, c1.y);
        xn[6]  = pk(a1.z, c1.z);  xn[7]  = pk(a1.w, c1.w);
        xn[8]  = pk(a2.x, c2.x);  xn[9]  = pk(a2.y, c2.y);
        xn[10] = pk(a2.z, c2.z);  xn[11] = pk(a2.w, c2.w);
        xn[12] = pk(a3.x, c3.x);  xn[13] = pk(a3.y, c3.y);
        xn[14] = pk(a3.z, c3.z);  xn[15] = pk(a3.w, c3.w);

        // ---- normalize over non-e0 blades: idx 0,2,3,4,8,9,10,14 ----
        u64 s2 = pk(1e-5f, 1e-5f);
        FMA2(s2, xn[0],  xn[0],  s2);
        FMA2(s2, xn[2],  xn[2],  s2);
        FMA2(s2, xn[3],  xn[3],  s2);
        FMA2(s2, xn[4],  xn[4],  s2);
        FMA2(s2, xn[8],  xn[8],  s2);
        FMA2(s2, xn[9],  xn[9],  s2);
        FMA2(s2, xn[10], xn[10], s2);
        FMA2(s2, xn[14], xn[14], s2);
        float sA, sB;  upk(sA, sB, s2);
        float rA = rsqrtf(sA), rB = rsqrtf(sB);
        u64 rinv2 = pk(rA, rB);
        u64 nrm2  = pk(sA * rA, sB * rB);      // sqrt(s): residual x = xn*nrm
        #pragma unroll
        for (int d = 0; d < 16; d++) MUL2(xn[d], xn[d], rinv2);

        // ---- first linear weights + exact GELU gate (folded into weights) ----
        const float4 w1a = *reinterpret_cast<const float4*>(w1);
        const float  w1e = w1[4];
        const float4 v1a = *reinterpret_cast<const float4*>(v1);

        u64 xp0_2;
        FMA2(xp0_2, bcast(w1a.x), xn[0], bcast(b1[0]));
        float xpA, xpB;  upk(xpA, xpB, xp0_2);
        u64 gate2 = pk(xpA * normcdff(xpA), xpB * normcdff(xpB));

        u64 W1[5], V1[4], xg0_2;
        MUL2(W1[0], gate2, bcast(w1a.x));
        MUL2(W1[1], gate2, bcast(w1a.y));
        MUL2(W1[2], gate2, bcast(w1a.z));
        MUL2(W1[3], gate2, bcast(w1a.w));
        MUL2(W1[4], gate2, bcast(w1e));
        MUL2(V1[0], gate2, bcast(v1a.x));
        MUL2(V1[1], gate2, bcast(v1a.y));
        MUL2(V1[2], gate2, bcast(v1a.z));
        MUL2(V1[3], gate2, bcast(v1a.w));
        MUL2(xg0_2, gate2, xp0_2);             // xg[0] (bias included)

        const u64 NEG1 = pk(-1.f, -1.f);

        // ---- geometric product + join, j-outer / i-inner, xg[j] on the fly ----
        u64 gp[16], jn[16];
        #pragma unroll
        for (int k = 0; k < 16; k++) { gp[k] = 0ull; jn[k] = 0ull; }

        #pragma unroll
        for (int j = 0; j < 16; j++) {
            const int mb = I2M(j);
            const int gB = pc4(mb);

            u64 xgj;
            if (j == 0) {
                xgj = xg0_2;
            } else {
                MUL2(xgj, W1[gB], xn[j]);
                if ((mb & 1) && gB < 4) FMA2(xgj, V1[gB], xn[M2I(mb ^ 1)], xgj);
            }
            u64 nxgj;
            MUL2(nxgj, xgj, NEG1);

            #pragma unroll
            for (int i = 0; i < 16; i++) {
                const int ma = I2M(i);
                if (!(ma & mb & 1)) {                      // e0^2 = 0
                    const int k = M2I(ma ^ mb);
                    const u64 op = (msign(ma, mb) > 0) ? xgj : nxgj;
                    FMA2(gp[k], xn[i], op, gp[k]);
                }
                if ((ma | mb) == 15) {                     // join support
                    const int k = M2I(ma & mb);
                    const u64 op = (jsign(ma, mb) > 0) ? xgj : nxgj;
                    FMA2(jn[k], xn[i], op, jn[k]);
                }
            }
        }

        // ---- output linears (x15 folded into join weights) + residual ----
        const float4 wga = *reinterpret_cast<const float4*>(wg);
        const float  wge = wg[4];
        const float4 vga = *reinterpret_cast<const float4*>(vg);
        const float4 wja = *reinterpret_cast<const float4*>(wj);
        const float  wje = wj[4];
        const float4 vja = *reinterpret_cast<const float4*>(vj);

        const u64 x15_2 = xn[15];
        u64 WG[5], VG[4], WJ[5], VJ[4];
        WG[0] = bcast(wga.x); WG[1] = bcast(wga.y); WG[2] = bcast(wga.z);
        WG[3] = bcast(wga.w); WG[4] = bcast(wge);
        VG[0] = bcast(vga.x); VG[1] = bcast(vga.y); VG[2] = bcast(vga.z);
        VG[3] = bcast(vga.w);
        MUL2(WJ[0], bcast(wja.x), x15_2);
        MUL2(WJ[1], bcast(wja.y), x15_2);
        MUL2(WJ[2], bcast(wja.z), x15_2);
        MUL2(WJ[3], bcast(wja.w), x15_2);
        MUL2(WJ[4], bcast(wje),   x15_2);
        MUL2(VJ[0], bcast(vja.x), x15_2);
        MUL2(VJ[1], bcast(vja.y), x15_2);
        MUL2(VJ[2], bcast(vja.z), x15_2);
        MUL2(VJ[3], bcast(vja.w), x15_2);

        u64 o[16];
        #pragma unroll
        for (int d = 0; d < 16; d++) {
            const int m = I2M(d);
            const int g = pc4(m);
            u64 v;
            MUL2(v, xn[d], nrm2);              // residual: original x[d]
            FMA2(v, WG[g], gp[d], v);
            FMA2(v, WJ[g], jn[d], v);
            if ((m & 1) && g < 4) {
                const int sidx = M2I(m ^ 1);
                FMA2(v, VG[g], gp[sidx], v);
                FMA2(v, VJ[g], jn[sidx], v);
            }
            o[d] = v;
        }
        {
            u64 bias2 = bcast(bg[0] + bj[0]);
            u64 one2  = pk(1.f, 1.f);
            FMA2(o[0], bias2, one2, o[0]);
        }

        // ---- unpack, write both tokens back into swizzled smem ----
        float oA[16], oB[16];
        #pragma unroll
        for (int d = 0; d < 16; d++) upk(oA[d], oB[d], o[d]);

        stage[swz(tid, 0)] = make_float4(oA[0],  oA[1],  oA[2],  oA[3]);
        stage[swz(tid, 1)] = make_float4(oA[4],  oA[5],  oA[6],  oA[7]);
        stage[swz(tid, 2)] = make_float4(oA[8],  oA[9],  oA[10], oA[11]);
        stage[swz(tid, 3)] = make_float4(oA[12], oA[13], oA[14], oA[15]);
        if (hasB) {
            stage[swz(lB, 0)] = make_float4(oB[0],  oB[1],  oB[2],  oB[3]);
            stage[swz(lB, 1)] = make_float4(oB[4],  oB[5],  oB[6],  oB[7]);
            stage[swz(lB, 2)] = make_float4(oB[8],  oB[9],  oB[10], oB[11]);
            stage[swz(lB, 3)] = make_float4(oB[12], oB[13], oB[14], oB[15]);
        }
    }
    __syncthreads();

    // ---- coalesced store from swizzled smem ----
    #pragma unroll
    for (int k = 0; k < 8; k++) {
        int f = tid + k * THREADS;
        if (f < nf4) out4[f] = stage[swz(f >> 2, f & 3)];
    }
}

extern "C" void kernel_launch(void* const* d_in, const int* in_sizes, int n_in,
                              void* d_out, int out_size)
{
    const float* x  = (const float*)d_in[0];
    const float* w1 = (const float*)d_in[1];
    const float* v1 = (const float*)d_in[2];
    const float* b1 = (const float*)d_in[3];
    const float* wg = (const float*)d_in[4];
    const float* vg = (const float*)d_in[5];
    const float* bg = (const float*)d_in[6];
    const float* wj = (const float*)d_in[7];
    const float* vj = (const float*)d_in[8];
    const float* bj = (const float*)d_in[9];

    const int ntok   = in_sizes[0] / 16;
    const int blocks = (ntok + TOKS - 1) / TOKS;

    mvffn_kernel<<<blocks, THREADS>>>(x, w1, v1, b1, wg, vg, bg, wj, vj, bj,
                                      (float*)d_out, ntok);
}